// round 1
// baseline (speedup 1.0000x reference)
#include <cuda_runtime.h>
#include <cstdint>

#define EPS 0.0001f

// ---------------- scratch (no allocations allowed) ----------------
__device__ float g_p2[2048];
__device__ float g_x2[64 * 196];

// ---------------- helpers ----------------
__device__ __forceinline__ void cp_async16(void* smem_dst, const void* gmem_src, bool valid) {
    uint32_t s = (uint32_t)__cvta_generic_to_shared(smem_dst);
    int sz = valid ? 16 : 0;
    asm volatile("cp.async.cg.shared.global [%0], [%1], 16, %2;\n"
                 :: "r"(s), "l"(gmem_src), "r"(sz));
}

__device__ __forceinline__ uint32_t f2tf32(float f) {
    uint32_t r;
    asm("cvt.rna.tf32.f32 %0, %1;" : "=r"(r) : "f"(f));
    return r;
}

__device__ __forceinline__ void mma_tf32(float* c, const uint32_t* a, const uint32_t* b) {
    asm volatile("mma.sync.aligned.m16n8k8.row.col.f32.tf32.tf32.f32 "
                 "{%0,%1,%2,%3}, {%4,%5,%6,%7}, {%8,%9}, {%0,%1,%2,%3};"
                 : "+f"(c[0]), "+f"(c[1]), "+f"(c[2]), "+f"(c[3])
                 : "r"(a[0]), "r"(a[1]), "r"(a[2]), "r"(a[3]),
                   "r"(b[0]), "r"(b[1]));
}

// ---------------- tiny precompute kernels ----------------
// p2[p] = sum_c proto[p][c]^2  (one warp per prototype, coalesced)
__global__ void p2_kernel(const float* __restrict__ proto) {
    int gw = (blockIdx.x * blockDim.x + threadIdx.x) >> 5;
    int lane = threadIdx.x & 31;
    if (gw >= 2000) return;
    const float* row = proto + (size_t)gw * 512;
    float s = 0.f;
    #pragma unroll 4
    for (int c = lane; c < 512; c += 32) { float v = row[c]; s = fmaf(v, v, s); }
    #pragma unroll
    for (int o = 16; o > 0; o >>= 1) s += __shfl_xor_sync(0xffffffffu, s, o);
    if (lane == 0) g_p2[gw] = s;
}

// x2[b*196+n] = sum_c x[b][c][n]^2  (thread per pixel; lanes coalesce over n)
__global__ void x2_kernel(const float* __restrict__ x) {
    int t = blockIdx.x * blockDim.x + threadIdx.x;
    if (t >= 64 * 196) return;
    int b = t / 196, n = t % 196;
    const float* base = x + (size_t)b * 512 * 196 + n;
    float s = 0.f;
    #pragma unroll 8
    for (int c = 0; c < 512; c++) { float v = base[c * 196]; s = fmaf(v, v, s); }
    g_x2[t] = s;
}

// ---------------- main GEMM + epilogue ----------------
// Per batch b: C[p][n] = sum_c proto[p][c] * x[b][c][n]
// M = 2000 (tiled by 128), N = 196 (padded to 208, one block covers all),
// K = 512 (tiled by 32), 3-stage cp.async pipeline, tf32 mma.sync.

constexpr int BM = 128, BN = 208, BK = 32, STAGES = 3;
constexpr int AW = 36;                 // A smem row width (bank-conflict-free: 36%32=4)
constexpr int BW = 216;                // B smem row width (216%32=24)
constexpr int A_ELEMS = BM * AW;       // 4608
constexpr int B_ELEMS = BK * BW;       // 6912
constexpr int STAGE_ELEMS = A_ELEMS + B_ELEMS;  // 11520
constexpr int SMEM_BYTES = STAGES * STAGE_ELEMS * 4;  // 138240

extern __shared__ float dynsmem[];

__global__ void __launch_bounds__(256, 1)
proto_gemm_kernel(const float* __restrict__ x,
                  const float* __restrict__ proto,
                  float* __restrict__ out) {
    const int b = blockIdx.y;
    const int pm0 = blockIdx.x * BM;
    const int tid = threadIdx.x;
    const int lane = tid & 31;
    const int warp = tid >> 5;
    const int wm = warp & 3;   // 4 warps over M (32 rows each)
    const int wn = warp >> 2;  // 2 warps over N (104 cols each)

    const float* xb = x + (size_t)b * (512 * 196);

    float acc[2][13][4];
    #pragma unroll
    for (int i = 0; i < 2; i++)
        #pragma unroll
        for (int t = 0; t < 13; t++)
            #pragma unroll
            for (int k = 0; k < 4; k++) acc[i][t][k] = 0.f;

    // ---- stage loader ----
    auto load_stage = [&](int kt, int buf) {
        float* as = dynsmem + buf * STAGE_ELEMS;
        float* bs = as + A_ELEMS;
        const int k0 = kt * BK;
        // A: 128 rows x 8 float4 (proto rows; zero-fill past M=2000)
        #pragma unroll
        for (int i = 0; i < 4; i++) {
            int idx = tid + i * 256;            // 1024 total
            int r = idx >> 3, c4 = idx & 7;
            bool v = (pm0 + r) < 2000;
            const float* g = proto + (size_t)(v ? (pm0 + r) : 0) * 512 + k0 + c4 * 4;
            cp_async16(as + r * AW + c4 * 4, g, v);
        }
        // B: 32 rows x 52 float4 (196 valid cols -> 49 full float4; rest zero)
        for (int idx = tid; idx < BK * 52; idx += 256) {
            int r = idx / 52, c4 = idx % 52;
            bool v = c4 < 49;
            const float* g = xb + (size_t)(k0 + r) * 196 + (v ? c4 * 4 : 0);
            cp_async16(bs + r * BW + c4 * 4, g, v);
        }
        asm volatile("cp.async.commit_group;");
    };

    // ---- compute one K-tile ----
    auto compute_stage = [&](int buf) {
        const float* as = dynsmem + buf * STAGE_ELEMS;
        const float* bs = as + A_ELEMS;
        const int ar = wm * 32 + (lane >> 2);
        const int bc = wn * 104 + (lane >> 2);
        #pragma unroll
        for (int k8 = 0; k8 < 4; k8++) {
            const int ac = k8 * 8 + (lane & 3);
            uint32_t afr[2][4];
            #pragma unroll
            for (int i = 0; i < 2; i++) {
                const float* ab = as + (ar + i * 16) * AW + ac;
                afr[i][0] = f2tf32(ab[0]);
                afr[i][1] = f2tf32(ab[8 * AW]);
                afr[i][2] = f2tf32(ab[4]);
                afr[i][3] = f2tf32(ab[8 * AW + 4]);
            }
            const int br = k8 * 8 + (lane & 3);
            uint32_t bfr[13][2];
            #pragma unroll
            for (int t = 0; t < 13; t++) {
                const float* bb = bs + br * BW + bc + t * 8;
                bfr[t][0] = f2tf32(bb[0]);
                bfr[t][1] = f2tf32(bb[4 * BW]);
            }
            #pragma unroll
            for (int i = 0; i < 2; i++)
                #pragma unroll
                for (int t = 0; t < 13; t++)
                    mma_tf32(acc[i][t], afr[i], bfr[t]);
        }
    };

    // ---- pipeline ----
    const int KT = 512 / BK;  // 16
    #pragma unroll
    for (int s = 0; s < STAGES - 1; s++) load_stage(s, s);

    for (int kt = 0; kt < KT; kt++) {
        asm volatile("cp.async.wait_group %0;" :: "n"(STAGES - 2));
        __syncthreads();
        int nk = kt + STAGES - 1;
        if (nk < KT) load_stage(nk, nk % STAGES);
        else         asm volatile("cp.async.commit_group;");
        compute_stage(kt % STAGES);
    }

    // ---- fused epilogue: dist -> log((dist+1)/(dist+EPS)) ----
    const int pr0 = pm0 + wm * 32 + (lane >> 2);
    const int nc0 = wn * 104 + (lane & 3) * 2;
    const float* x2p = g_x2 + b * 196;
    float* outb = out + (size_t)b * 2000 * 196;

    #pragma unroll
    for (int i = 0; i < 2; i++) {
        #pragma unroll
        for (int half = 0; half < 2; half++) {
            int p = pr0 + i * 16 + half * 8;
            if (p >= 2000) continue;
            float p2 = g_p2[p];
            float* orow = outb + (size_t)p * 196;
            #pragma unroll
            for (int t = 0; t < 13; t++) {
                int n = nc0 + t * 8;
                #pragma unroll
                for (int j = 0; j < 2; j++) {
                    if (n + j < 196) {
                        float xp = acc[i][t][half * 2 + j];
                        float d = fmaxf(x2p[n + j] + p2 - 2.f * xp, 0.f);
                        // log((d+1)/(d+EPS)) == log1p((1-EPS)/(d+EPS))
                        orow[n + j] = log1pf((1.f - EPS) / (d + EPS));
                    }
                }
            }
        }
    }
}

// ---------------- launch ----------------
extern "C" void kernel_launch(void* const* d_in, const int* in_sizes, int n_in,
                              void* d_out, int out_size) {
    const float* x = (const float*)d_in[0];      // (64, 512, 14, 14)
    const float* proto = (const float*)d_in[1];  // (2000, 512, 1, 1)
    float* out = (float*)d_out;                  // (64, 2000, 14, 14)

    (void)in_sizes; (void)n_in; (void)out_size;

    p2_kernel<<<(2000 * 32 + 255) / 256, 256>>>(proto);
    x2_kernel<<<(64 * 196 + 255) / 256, 256>>>(x);

    cudaFuncSetAttribute(proto_gemm_kernel,
                         cudaFuncAttributeMaxDynamicSharedMemorySize, SMEM_BYTES);
    dim3 grid(16, 64);  // 16 M-tiles x 64 batches
    proto_gemm_kernel<<<grid, 256, SMEM_BYTES>>>(x, proto, out);
}

// round 4
// speedup vs baseline: 1.4805x; 1.4805x over previous
#include <cuda_runtime.h>
#include <cuda_bf16.h>
#include <cstdint>
#include <cstddef>

#define EPS 0.0001f

// ---------------- static device scratch ----------------
__device__ float g_p2[2048];
__device__ float g_x2[64 * 196];
__device__ __nv_bfloat16 g_pB[2048 * 512];                    // proto bf16, rows >=2000 zero
__device__ __nv_bfloat16 g_xTB[(size_t)64 * 224 * 512];       // x^T bf16: [b][n pad224][c], pad rows zero

// ---------------- PTX helpers ----------------
__device__ __forceinline__ uint32_t smem_u32(const void* p) {
    uint32_t a;
    asm("{ .reg .u64 t; cvta.to.shared.u64 t, %1; cvt.u32.u64 %0, t; }" : "=r"(a) : "l"(p));
    return a;
}

__device__ __forceinline__ void cp_async16(uint32_t smem_dst, const void* gmem_src) {
    asm volatile("cp.async.cg.shared.global [%0], [%1], 16;\n"
                 :: "r"(smem_dst), "l"(gmem_src));
}

#define CP_COMMIT() asm volatile("cp.async.commit_group;")
#define CP_WAIT(n)  asm volatile("cp.async.wait_group %0;" :: "n"(n))

#define LDSM_X4(r0, r1, r2, r3, addr) \
    asm volatile("ldmatrix.sync.aligned.m8n8.x4.shared.b16 {%0,%1,%2,%3}, [%4];" \
                 : "=r"(r0), "=r"(r1), "=r"(r2), "=r"(r3) : "r"(addr))

#define LDSM_X2(r0, r1, addr) \
    asm volatile("ldmatrix.sync.aligned.m8n8.x2.shared.b16 {%0,%1}, [%2];" \
                 : "=r"(r0), "=r"(r1) : "r"(addr))

__device__ __forceinline__ void mma_bf16(float* c, const uint32_t* a, const uint32_t* b) {
    asm volatile("mma.sync.aligned.m16n8k16.row.col.f32.bf16.bf16.f32 "
                 "{%0,%1,%2,%3}, {%4,%5,%6,%7}, {%8,%9}, {%0,%1,%2,%3};"
                 : "+f"(c[0]), "+f"(c[1]), "+f"(c[2]), "+f"(c[3])
                 : "r"(a[0]), "r"(a[1]), "r"(a[2]), "r"(a[3]),
                   "r"(b[0]), "r"(b[1]));
}

// ---------------- precompute kernels ----------------
__global__ void p2_kernel(const float* __restrict__ proto) {
    int gw = (blockIdx.x * blockDim.x + threadIdx.x) >> 5;
    int lane = threadIdx.x & 31;
    if (gw >= 2000) return;
    const float* row = proto + (size_t)gw * 512;
    float s = 0.f;
    #pragma unroll 4
    for (int c = lane; c < 512; c += 32) { float v = row[c]; s = fmaf(v, v, s); }
    #pragma unroll
    for (int o = 16; o > 0; o >>= 1) s += __shfl_xor_sync(0xffffffffu, s, o);
    if (lane == 0) g_p2[gw] = s;
}

__global__ void x2_kernel(const float* __restrict__ x) {
    int t = blockIdx.x * blockDim.x + threadIdx.x;
    if (t >= 64 * 196) return;
    int b = t / 196, n = t % 196;
    const float* base = x + (size_t)b * 512 * 196 + n;
    float s = 0.f;
    #pragma unroll 8
    for (int c = 0; c < 512; c++) { float v = base[c * 196]; s = fmaf(v, v, s); }
    g_x2[t] = s;
}

__global__ void cvt_proto_kernel(const float* __restrict__ proto) {
    int i = blockIdx.x * blockDim.x + threadIdx.x;
    if (i >= 2048 * 512) return;
    int p = i >> 9;
    g_pB[i] = (p < 2000) ? __float2bfloat16(proto[i]) : __float2bfloat16(0.f);
}

// transpose+convert x[b][c][n] -> g_xTB[b][n][c] (bf16, n padded to 224, pad rows zero)
__global__ void transpose_bf_kernel(const float* __restrict__ x) {
    __shared__ float t[32][33];
    int b = blockIdx.z;
    int n0 = blockIdx.x * 32, c0 = blockIdx.y * 32;
    int tx = threadIdx.x, ty = threadIdx.y;
    const float* xb = x + (size_t)b * 512 * 196;
    #pragma unroll
    for (int i = 0; i < 32; i += 8) {
        int c = c0 + ty + i, n = n0 + tx;
        t[ty + i][tx] = (n < 196) ? xb[(size_t)c * 196 + n] : 0.f;
    }
    __syncthreads();
    __nv_bfloat16* ob = g_xTB + (size_t)b * 224 * 512;
    #pragma unroll
    for (int i = 0; i < 32; i += 8) {
        int n = n0 + ty + i, c = c0 + tx;
        ob[(size_t)n * 512 + c] = __float2bfloat16(t[tx][ty + i]);
    }
}

// ---------------- main persistent-A bf16 mma kernel ----------------
// grid (16 M-tiles, 8 batch-groups) = 128 CTAs, 512 threads.
// Each CTA: A tile (128 protos x 512 k) resident in smem; loops 8 batches x 16 k-tiles,
// streaming B (x^T) tiles through a 3-stage cp.async pipeline.

constexpr int A_STRIDE = 1040;                     // 1024 data + 16 pad (ldmatrix conflict-free)
constexpr int A_BYTES = 128 * A_STRIDE;            // 133120
constexpr int B_STRIDE = 80;                       // 64 data + 16 pad
constexpr int B_TILE_BYTES = 224 * B_STRIDE;       // 17920
constexpr int BSTAGES = 3;
constexpr int SMEM_TOTAL = A_BYTES + BSTAGES * B_TILE_BYTES;  // 186880

__global__ void __launch_bounds__(512, 1)
proto_mma_kernel(float* __restrict__ out) {
    extern __shared__ __align__(16) char sm[];
    const uint32_t sbase = smem_u32(sm);
    const uint32_t bbase0 = sbase + A_BYTES;

    const int tid = threadIdx.x;
    const int lane = tid & 31;
    const int warp = tid >> 5;            // 0..15
    const int wm = warp & 3;              // 4 warps over M (32 rows each)
    const int wn = warp >> 2;             // 4 warps over N (56 cols each)
    const int mt = blockIdx.x;            // M-tile 0..15
    const int bg = blockIdx.y;            // batch group 0..7
    const int pm0 = mt * 128;

    // ---- load A tile (128 rows x 512 k bf16 = 64 x 16B chunks per row) once ----
    {
        const __nv_bfloat16* gA = g_pB + (size_t)pm0 * 512;
        for (int idx = tid; idx < 8192; idx += 512) {
            int r = idx >> 6, c = idx & 63;
            cp_async16(sbase + r * A_STRIDE + c * 16, gA + (size_t)r * 512 + c * 8);
        }
    }

    // ---- B tile loader: T = global tile index (b_local*16 + kt) ----
    auto loadB = [&](int T) {
        const int slot = T % BSTAGES;
        const int b = bg * 8 + (T >> 4);
        const int kt = T & 15;
        const __nv_bfloat16* gB = g_xTB + (size_t)b * 224 * 512 + kt * 32;
        const uint32_t dst = bbase0 + slot * B_TILE_BYTES;
        for (int idx = tid; idx < 896; idx += 512) {
            int r = idx >> 2, c = idx & 3;
            cp_async16(dst + r * B_STRIDE + c * 16, gB + (size_t)r * 512 + c * 8);
        }
    };

    loadB(0); CP_COMMIT();   // group0 = A + B0
    loadB(1); CP_COMMIT();   // group1 = B1

    // ---- per-thread invariants ----
    float p2v[2][2];
    #pragma unroll
    for (int i = 0; i < 2; i++)
        #pragma unroll
        for (int h = 0; h < 2; h++) {
            int p = pm0 + wm * 32 + i * 16 + (lane >> 2) + h * 8;
            p2v[i][h] = g_p2[p];
        }

    const uint32_t a_l_off = sbase + (wm * 32 + (lane & 15)) * A_STRIDE + (lane >> 4) * 16;
    const uint32_t b_l_off = (wn * 56 + (lane & 7)) * B_STRIDE + ((lane >> 3) & 1) * 16;

    float acc[2][7][4];
    #pragma unroll
    for (int i = 0; i < 2; i++)
        #pragma unroll
        for (int t = 0; t < 7; t++)
            #pragma unroll
            for (int e = 0; e < 4; e++) acc[i][t][e] = 0.f;

    const int NT = 8 * 16;  // 128 tiles
    for (int T = 0; T < NT; T++) {
        CP_WAIT(1);
        __syncthreads();
        if (T + 2 < NT) loadB(T + 2);
        CP_COMMIT();

        // ---- compute tile T ----
        const int kt = T & 15;
        const uint32_t abase = a_l_off + kt * 64;
        const uint32_t bbase = bbase0 + (T % BSTAGES) * B_TILE_BYTES + b_l_off;

        #pragma unroll
        for (int s = 0; s < 2; s++) {          // two k16 steps per 32-k tile
            uint32_t afr[2][4];
            LDSM_X4(afr[0][0], afr[0][1], afr[0][2], afr[0][3], abase + s * 32);
            LDSM_X4(afr[1][0], afr[1][1], afr[1][2], afr[1][3], abase + 16 * A_STRIDE + s * 32);
            uint32_t bfr[7][2];
            #pragma unroll
            for (int t = 0; t < 7; t++)
                LDSM_X2(bfr[t][0], bfr[t][1], bbase + t * 8 * B_STRIDE + s * 32);
            #pragma unroll
            for (int i = 0; i < 2; i++)
                #pragma unroll
                for (int t = 0; t < 7; t++)
                    mma_bf16(acc[i][t], afr[i], bfr[t]);
        }

        // ---- batch boundary: fused epilogue + accumulator reset ----
        if ((T & 15) == 15) {
            const int b = bg * 8 + (T >> 4);
            const float* x2b = g_x2 + b * 196;
            float* outb = out + (size_t)b * 2000 * 196;
            #pragma unroll
            for (int i = 0; i < 2; i++) {
                #pragma unroll
                for (int h = 0; h < 2; h++) {
                    const int p = pm0 + wm * 32 + i * 16 + (lane >> 2) + h * 8;
                    const bool pok = p < 2000;
                    const float pv = p2v[i][h];
                    float* orow = outb + (size_t)p * 196;
                    #pragma unroll
                    for (int t = 0; t < 7; t++) {
                        const int n = wn * 56 + t * 8 + (lane & 3) * 2;
                        if (pok && n < 196) {
                            float xp0 = acc[i][t][h * 2 + 0];
                            float xp1 = acc[i][t][h * 2 + 1];
                            float d0 = fmaxf(fmaf(-2.f, xp0, x2b[n] + pv), 0.f);
                            float d1 = fmaxf(fmaf(-2.f, xp1, x2b[n + 1] + pv), 0.f);
                            float2 v;
                            v.x = log1pf((1.f - EPS) / (d0 + EPS));
                            v.y = log1pf((1.f - EPS) / (d1 + EPS));
                            *(float2*)(orow + n) = v;
                        }
                    }
                }
            }
            #pragma unroll
            for (int i = 0; i < 2; i++)
                #pragma unroll
                for (int t = 0; t < 7; t++)
                    #pragma unroll
                    for (int e = 0; e < 4; e++) acc[i][t][e] = 0.f;
        }
    }
}

// ---------------- launch ----------------
extern "C" void kernel_launch(void* const* d_in, const int* in_sizes, int n_in,
                              void* d_out, int out_size) {
    const float* x = (const float*)d_in[0];      // (64, 512, 14, 14)
    const float* proto = (const float*)d_in[1];  // (2000, 512, 1, 1)
    float* out = (float*)d_out;                  // (64, 2000, 14, 14)
    (void)in_sizes; (void)n_in; (void)out_size;

    p2_kernel<<<(2000 * 32 + 255) / 256, 256>>>(proto);
    x2_kernel<<<(64 * 196 + 255) / 256, 256>>>(x);
    cvt_proto_kernel<<<(2048 * 512) / 256, 256>>>(proto);
    transpose_bf_kernel<<<dim3(7, 16, 64), dim3(32, 8)>>>(x);

    cudaFuncSetAttribute(proto_mma_kernel,
                         cudaFuncAttributeMaxDynamicSharedMemorySize, SMEM_TOTAL);
    proto_mma_kernel<<<dim3(16, 8), 512, SMEM_TOTAL>>>(out);
}